// round 13
// baseline (speedup 1.0000x reference)
#include <cuda_runtime.h>
#include <cuda_fp16.h>
#include <cstdint>

#define SLEN 2048
#define HDIM 768
#define HD 64
#define NHEADS 12
#define NBH 48
#define NBATCH 4

// fp16 scratch
__device__ __half g_X [(size_t)3 * NBATCH * SLEN * HDIM];   // [mod][b][s][h]
__device__ __half g_Wt[(size_t)3 * NHEADS * HD * HDIM];     // [which][head][d][h]
__device__ __half g_Q [(size_t)NBH * SLEN * HD];            // pre-scaled by 0.125*log2(e)
__device__ __half g_K [(size_t)NBH * SLEN * HD];
__device__ __half g_Vt[(size_t)NBH * HD * SLEN];            // [bh][d][s]

// ---------------------------------------------------------------------------
__device__ __forceinline__ uint32_t smem_u32(const void* p) {
    uint32_t a;
    asm("{ .reg .u64 t; cvta.to.shared.u64 t, %1; cvt.u32.u64 %0, t; }"
        : "=r"(a) : "l"(p));
    return a;
}
__device__ __forceinline__ void ldsm4(uint32_t a, uint32_t r[4]) {
    asm volatile("ldmatrix.sync.aligned.m8n8.x4.shared.b16 {%0,%1,%2,%3}, [%4];"
                 : "=r"(r[0]), "=r"(r[1]), "=r"(r[2]), "=r"(r[3]) : "r"(a));
}
__device__ __forceinline__ void mma_h(float d[4], const uint32_t a[4],
                                      uint32_t b0, uint32_t b1) {
    asm volatile(
        "mma.sync.aligned.m16n8k16.row.col.f32.f16.f16.f32 "
        "{%0,%1,%2,%3}, {%4,%5,%6,%7}, {%8,%9}, {%0,%1,%2,%3};"
        : "+f"(d[0]), "+f"(d[1]), "+f"(d[2]), "+f"(d[3])
        : "r"(a[0]), "r"(a[1]), "r"(a[2]), "r"(a[3]), "r"(b0), "r"(b1));
}
__device__ __forceinline__ uint32_t ex2_h2(uint32_t x) {
    uint32_t r;
    asm("ex2.approx.f16x2 %0, %1;" : "=r"(r) : "r"(x));
    return r;
}
__device__ __forceinline__ uint32_t hadd2u(uint32_t a, uint32_t b) {
    uint32_t r;
    asm("add.f16x2 %0, %1, %2;" : "=r"(r) : "r"(a), "r"(b));
    return r;
}
// tile rows are 128B (64 halves); 8 x 16B chunks, XOR swizzle
__device__ __forceinline__ uint32_t sw_off(int row, int chunk) {
    return (uint32_t)(row * 128 + ((chunk ^ (row & 7)) << 4));
}
#define CP16(dst, src) \
    asm volatile("cp.async.cg.shared.global [%0], [%1], 16;" :: "r"(dst), "l"(src))
#define CPC() asm volatile("cp.async.commit_group;" ::: "memory")
#define CPW0() asm volatile("cp.async.wait_group 0;" ::: "memory")

__device__ __forceinline__ uint32_t pack_h2(float a, float b) {
    __half2 h = __floats2half2_rn(a, b);
    return *(uint32_t*)&h;
}

// ---------------------------------------------------------------------------
// X conversion: modality = blockIdx.y, contiguous float4 per thread.
// ---------------------------------------------------------------------------
__global__ __launch_bounds__(256) void conv_x(const float* __restrict__ e1,
                                              const float* __restrict__ e2,
                                              const float* __restrict__ e3) {
    const int mod = blockIdx.y;
    const float* src = mod == 0 ? e1 : (mod == 1 ? e2 : e3);
    size_t idx = (size_t)blockIdx.x * 256 + threadIdx.x;   // < 4*2048*768/4
    const float4 v = ((const float4*)src)[idx];
    uint2 o = { pack_h2(v.x, v.y), pack_h2(v.z, v.w) };
    ((uint2*)g_X)[(size_t)mod * (NBATCH * SLEN * HDIM / 4) + idx] = o;
}

// W transpose via smem tiles: Wt[which][head][d][hh] = W[head][hh][d].
__global__ __launch_bounds__(256) void conv_w(const float* __restrict__ Wq,
                                              const float* __restrict__ Wk,
                                              const float* __restrict__ Wv) {
    __shared__ float tile[32][33];
    const int tx = threadIdx.x & 31, ty = threadIdx.x >> 5;   // ty 0..7
    const int hh0 = blockIdx.x * 32, d0 = blockIdx.y * 32;
    const int wh = blockIdx.z;                 // which*12 + head
    const int which = wh / NHEADS, head = wh % NHEADS;
    const float* W = which == 0 ? Wq : (which == 1 ? Wk : Wv);
    const float* Ws = W + (size_t)head * HDIM * HD;

    #pragma unroll
    for (int j = 0; j < 4; j++) {
        int hh = ty * 4 + j;
        tile[hh][tx] = Ws[(size_t)(hh0 + hh) * HD + d0 + tx];
    }
    __syncthreads();
    __half* dst = g_Wt + ((size_t)wh * HD + d0) * HDIM + hh0;
    #pragma unroll
    for (int j = 0; j < 4; j++) {
        int d = ty * 4 + j;
        dst[(size_t)d * HDIM + tx] = __float2half_rn(tile[tx][d]);
    }
}

// ---------------------------------------------------------------------------
// Projection: block (sT 0..7, bh 0..47, which 0..2), 128 threads (4 warps),
// 256-row s-tile, 64 rows per warp (4 m-tiles). cp.async double-buffered.
// ---------------------------------------------------------------------------
__global__ __launch_bounds__(128, 2) void proj_mma(const float* __restrict__ bq,
                                                   const float* __restrict__ bk,
                                                   const float* __restrict__ bv) {
    extern __shared__ char smraw[];
    char* sm = (char*)(((uintptr_t)smraw + 127) & ~(uintptr_t)127);
    char* Xb[2] = { sm, sm + 32768 };           // 32KB each (256 rows)
    char* Wb[2] = { sm + 65536, sm + 73728 };   // 8KB each

    const int tid = threadIdx.x, lane = tid & 31, wid = tid >> 5;
    const int sT = blockIdx.x, bh = blockIdx.y, which = blockIdx.z;
    const int b = bh / NHEADS, h = bh % NHEADS, g = h >> 2;

    const __half* Xg = g_X + ((size_t)(g * NBATCH + b) * SLEN + (size_t)sT * 256) * HDIM;
    const __half* Wg = g_Wt + ((size_t)(which * NHEADS + h) * HD) * HDIM;

    const uint32_t sX[2] = { smem_u32(Xb[0]), smem_u32(Xb[1]) };
    const uint32_t sW[2] = { smem_u32(Wb[0]), smem_u32(Wb[1]) };

    auto prefetch = [&](int ch, int bf) {
        #pragma unroll
        for (int i = tid; i < 2048; i += 128) {          // X: 256 rows x 8 chunks
            int r = i >> 3, c = i & 7;
            CP16(sX[bf] + sw_off(r, c), (const char*)(Xg + (size_t)r * HDIM + ch * 64 + c * 8));
        }
        #pragma unroll
        for (int i = tid; i < 512; i += 128) {           // W: 64 rows x 8 chunks
            int r = i >> 3, c = i & 7;
            CP16(sW[bf] + sw_off(r, c), (const char*)(Wg + (size_t)r * HDIM + ch * 64 + c * 8));
        }
    };

    prefetch(0, 0);
    CPC();
    CPW0();
    __syncthreads();

    const int aRow0 = wid * 64 + (lane & 15);
    const int aChk = lane >> 4;
    const int bRow = (lane & 7) + ((lane >> 4) << 3);
    const int bChk = (lane >> 3) & 1;

    float acc[4][8][4] = {};

    for (int ch = 0; ch < 12; ch++) {
        if (ch < 11) { prefetch(ch + 1, (ch + 1) & 1); CPC(); }
        const int bf = ch & 1;
        #pragma unroll
        for (int ks = 0; ks < 4; ks++) {
            uint32_t a[4][4];
            #pragma unroll
            for (int mt = 0; mt < 4; mt++)
                ldsm4(sX[bf] + sw_off(aRow0 + mt * 16, ks * 2 + aChk), a[mt]);
            #pragma unroll
            for (int np = 0; np < 4; np++) {
                uint32_t bfr[4];
                ldsm4(sW[bf] + sw_off(np * 16 + bRow, ks * 2 + bChk), bfr);
                #pragma unroll
                for (int mt = 0; mt < 4; mt++) {
                    mma_h(acc[mt][2 * np],     a[mt], bfr[0], bfr[1]);
                    mma_h(acc[mt][2 * np + 1], a[mt], bfr[2], bfr[3]);
                }
            }
        }
        if (ch < 11) { CPW0(); __syncthreads(); }
    }

    const float* bias = (which == 0 ? bq : (which == 1 ? bk : bv)) + h * HD;
    // Q pre-scale: 1/sqrt(64) * log2(e), so attention can use exp2.
    const float scale = (which == 0) ? 0.125f * 1.44269504f : 1.0f;

    if (which < 2) {
        __half* D = (which == 0 ? g_Q : g_K) + ((size_t)bh * SLEN + (size_t)sT * 256) * HD;
        #pragma unroll
        for (int mt = 0; mt < 4; mt++) {
            #pragma unroll
            for (int nt = 0; nt < 8; nt++) {
                int d = nt * 8 + 2 * (lane & 3);
                float b0 = bias[d], b1 = bias[d + 1];
                #pragma unroll
                for (int rr = 0; rr < 2; rr++) {
                    int srow = wid * 64 + mt * 16 + (lane >> 2) + rr * 8;
                    uint32_t v = pack_h2((acc[mt][nt][2 * rr] + b0) * scale,
                                         (acc[mt][nt][2 * rr + 1] + b1) * scale);
                    *(uint32_t*)(D + (size_t)srow * HD + d) = v;
                }
            }
        }
    } else {
        __syncthreads();
        __half* Vs = (__half*)Xb[0];   // stage transposed [64 d][256 s] = 32KB
        #pragma unroll
        for (int mt = 0; mt < 4; mt++) {
            #pragma unroll
            for (int nt = 0; nt < 8; nt++) {
                int d = nt * 8 + 2 * (lane & 3);
                float b0 = bias[d], b1 = bias[d + 1];
                #pragma unroll
                for (int rr = 0; rr < 2; rr++) {
                    int srow = wid * 64 + mt * 16 + (lane >> 2) + rr * 8;
                    Vs[d * 256 + srow]       = __float2half_rn(acc[mt][nt][2 * rr] + b0);
                    Vs[(d + 1) * 256 + srow] = __float2half_rn(acc[mt][nt][2 * rr + 1] + b1);
                }
            }
        }
        __syncthreads();
        #pragma unroll
        for (int i = tid; i < 2048; i += 128) {
            int r = i >> 5, c = i & 31;
            *(uint4*)(g_Vt + ((size_t)bh * HD + r) * SLEN + (size_t)sT * 256 + c * 8) =
                *(uint4*)(Vs + r * 256 + c * 8);
        }
    }
}

// ---------------------------------------------------------------------------
// Attention: block (qT 0..15, bh 0..47), 128 threads (4 warps x 32 q-rows).
// 128-key outer tiles (one barrier each); inner work in 16-key groups:
// QK (16 regs) -> ex2 (8 regs, directly the PV A-frag) -> PV. Small live set,
// and group n+1's QK MMAs overlap group n's MUFU/PV in the scheduler.
// ---------------------------------------------------------------------------
__global__ __launch_bounds__(128, 2) void attn_mma(float* __restrict__ out) {
    extern __shared__ char smraw[];
    char* sm = (char*)(((uintptr_t)smraw + 127) & ~(uintptr_t)127);
    char* Qs = sm;                                               // 16KB
    char* Kst[2][2] = { { sm + 16384, sm + 24576 }, { sm + 32768, sm + 40960 } };
    char* Vst[2][2] = { { sm + 49152, sm + 57344 }, { sm + 65536, sm + 73728 } };

    const int tid = threadIdx.x, lane = tid & 31, wid = tid >> 5;
    const int qT = blockIdx.x, bh = blockIdx.y;
    const int b = bh / NHEADS, h = bh % NHEADS;

    const uint32_t sQ = smem_u32(Qs);
    uint32_t sK[2][2], sV[2][2];
    #pragma unroll
    for (int i = 0; i < 2; i++)
        #pragma unroll
        for (int j = 0; j < 2; j++) {
            sK[i][j] = smem_u32(Kst[i][j]);
            sV[i][j] = smem_u32(Vst[i][j]);
        }

    const __half* Qg = g_Q + ((size_t)bh * SLEN + (size_t)qT * 128) * HD;
    const __half* Kg = g_K + (size_t)bh * SLEN * HD;
    const __half* Vg = g_Vt + (size_t)bh * HD * SLEN;

    // Load one 128-key tile (two 64-key sub-tiles) into buffer bf.
    auto prefetch = [&](int t, int bf) {
        #pragma unroll
        for (int i = tid; i < 1024; i += 128) {          // K: 128 rows x 8 chunks
            int r = i >> 3, c = i & 7;
            CP16(sK[bf][r >> 6] + sw_off(r & 63, c),
                 (const char*)(Kg + ((size_t)t * 128 + r) * HD + c * 8));
        }
        #pragma unroll
        for (int i = tid; i < 1024; i += 128) {          // V: 64 d-rows x 16 chunks
            int r = i >> 4, c = i & 15;
            CP16(sV[bf][c >> 3] + sw_off(r, c & 7),
                 (const char*)(Vg + (size_t)r * SLEN + t * 128 + c * 8));
        }
    };

    #pragma unroll
    for (int i = tid; i < 1024; i += 128) {
        int r = i >> 3, c = i & 7;
        CP16(sQ + sw_off(r, c), (const char*)(Qg + (size_t)r * HD + c * 8));
    }
    prefetch(0, 0);
    CPC();
    CPW0();
    __syncthreads();

    const int aRow0 = wid * 32 + (lane & 15);
    const int aChk = lane >> 4;
    const int bRow = (lane & 7) + ((lane >> 4) << 3);
    const int bChk = (lane >> 3) & 1;

    // Hoist Q A-fragments (loop-invariant): 2 m-tiles x 4 k-steps
    uint32_t ahq[2][4][4];
    #pragma unroll
    for (int mt = 0; mt < 2; mt++)
        #pragma unroll
        for (int ks = 0; ks < 4; ks++)
            ldsm4(sQ + sw_off(aRow0 + mt * 16, ks * 2 + aChk), ahq[mt][ks]);

    float oacc[2][8][4] = {};
    float rs[2][2] = {};     // [mt][row-group], fp32 rowsum accumulators

    for (int t = 0; t < 16; t++) {
        if (t < 15) { prefetch(t + 1, (t + 1) & 1); CPC(); }
        const int bf = t & 1;

        #pragma unroll
        for (int hf = 0; hf < 2; hf++) {
            #pragma unroll
            for (int kg = 0; kg < 4; kg++) {     // 16-key groups
                // S = Q K^T for keys [kg*16, kg*16+16)
                float sacc[2][2][4] = {};        // [mt][n8][4]
                #pragma unroll
                for (int ks = 0; ks < 4; ks++) {
                    uint32_t kf[4];
                    ldsm4(sK[bf][hf] + sw_off(kg * 16 + bRow, ks * 2 + bChk), kf);
                    #pragma unroll
                    for (int mt = 0; mt < 2; mt++) {
                        mma_h(sacc[mt][0], ahq[mt][ks], kf[0], kf[1]);
                        mma_h(sacc[mt][1], ahq[mt][ks], kf[2], kf[3]);
                    }
                }

                // P = 2^S: 8 ex2.f16x2 -> ph == PV A-fragments (k=16 keys)
                uint32_t ph[2][4];
                #pragma unroll
                for (int mt = 0; mt < 2; mt++) {
                    ph[mt][0] = ex2_h2(pack_h2(sacc[mt][0][0], sacc[mt][0][1]));
                    ph[mt][1] = ex2_h2(pack_h2(sacc[mt][0][2], sacc[mt][0][3]));
                    ph[mt][2] = ex2_h2(pack_h2(sacc[mt][1][0], sacc[mt][1][1]));
                    ph[mt][3] = ex2_h2(pack_h2(sacc[mt][1][2], sacc[mt][1][3]));
                    // rowsum: rg0 = row r (ph[0], ph[2]); rg1 = row r+8 (ph[1], ph[3])
                    uint32_t s0 = hadd2u(ph[mt][0], ph[mt][2]);
                    uint32_t s1 = hadd2u(ph[mt][1], ph[mt][3]);
                    float2 f0 = __half22float2(*(__half2*)&s0);
                    float2 f1 = __half22float2(*(__half2*)&s1);
                    rs[mt][0] += f0.x + f0.y;
                    rs[mt][1] += f1.x + f1.y;
                }

                // O += P V over these 16 keys (V chunk pair = kg)
                #pragma unroll
                for (int nv = 0; nv < 4; nv++) {
                    uint32_t vf[4];
                    ldsm4(sV[bf][hf] + sw_off(nv * 16 + bRow, kg * 2 + bChk), vf);
                    #pragma unroll
                    for (int mt = 0; mt < 2; mt++) {
                        mma_h(oacc[mt][2 * nv],     ph[mt], vf[0], vf[1]);
                        mma_h(oacc[mt][2 * nv + 1], ph[mt], vf[2], vf[3]);
                    }
                }
            }
        }
        if (t < 15) { CPW0(); __syncthreads(); }
    }

    // Rowsum reduce across the quad (columns spread over lane%4)
    #pragma unroll
    for (int mt = 0; mt < 2; mt++)
        #pragma unroll
        for (int rg = 0; rg < 2; rg++) {
            float v = rs[mt][rg];
            v += __shfl_xor_sync(0xffffffffu, v, 1);
            v += __shfl_xor_sync(0xffffffffu, v, 2);
            rs[mt][rg] = v;
        }

    // Write output: out[b][s][h*64 + d]
    int r = lane >> 2;
    #pragma unroll
    for (int mt = 0; mt < 2; mt++) {
        float inv0 = 1.0f / rs[mt][0];
        float inv1 = 1.0f / rs[mt][1];
        int srow0 = qT * 128 + wid * 32 + mt * 16 + r;
        #pragma unroll
        for (int nt = 0; nt < 8; nt++) {
            int d = nt * 8 + 2 * (lane & 3);
            float2 v0 = { oacc[mt][nt][0] * inv0, oacc[mt][nt][1] * inv0 };
            float2 v1 = { oacc[mt][nt][2] * inv1, oacc[mt][nt][3] * inv1 };
            *(float2*)&out[((size_t)b * SLEN + srow0)     * HDIM + h * HD + d] = v0;
            *(float2*)&out[((size_t)b * SLEN + srow0 + 8) * HDIM + h * HD + d] = v1;
        }
    }
}

// ---------------------------------------------------------------------------
extern "C" void kernel_launch(void* const* d_in, const int* in_sizes, int n_in,
                              void* d_out, int out_size) {
    const float* e1 = (const float*)d_in[0];
    const float* e2 = (const float*)d_in[1];
    const float* e3 = (const float*)d_in[2];
    const float* Wq = (const float*)d_in[3];
    const float* bq = (const float*)d_in[4];
    const float* Wk = (const float*)d_in[5];
    const float* bk = (const float*)d_in[6];
    const float* Wv = (const float*)d_in[7];
    const float* bv = (const float*)d_in[8];
    float* out = (float*)d_out;

    conv_x<<<dim3(6144, 3), 256>>>(e1, e2, e3);
    conv_w<<<dim3(24, 2, 36), 256>>>(Wq, Wk, Wv);

    const int smProj = 81920 + 256;
    const int smAttn = 81920 + 256;
    cudaFuncSetAttribute(proj_mma, cudaFuncAttributeMaxDynamicSharedMemorySize, smProj);
    cudaFuncSetAttribute(attn_mma, cudaFuncAttributeMaxDynamicSharedMemorySize, smAttn);

    proj_mma<<<dim3(8, 48, 3), 128, smProj>>>(bq, bk, bv);
    attn_mma<<<dim3(16, 48), 128, smAttn>>>(out);
}

// round 14
// speedup vs baseline: 1.0320x; 1.0320x over previous
#include <cuda_runtime.h>
#include <cuda_fp16.h>
#include <cstdint>

#define SLEN 2048
#define HDIM 768
#define HD 64
#define NHEADS 12
#define NBH 48
#define NBATCH 4

// fp16 scratch
__device__ __half g_X [(size_t)3 * NBATCH * SLEN * HDIM];   // [mod][b][s][h]
__device__ __half g_Wt[(size_t)3 * NHEADS * HD * HDIM];     // [which][head][d][h]
__device__ __half g_Q [(size_t)NBH * SLEN * HD];            // pre-scaled by 0.125*log2(e)
__device__ __half g_K [(size_t)NBH * SLEN * HD];
__device__ __half g_V [(size_t)NBH * SLEN * HD];            // natural [bh][s][d]

// ---------------------------------------------------------------------------
__device__ __forceinline__ uint32_t smem_u32(const void* p) {
    uint32_t a;
    asm("{ .reg .u64 t; cvta.to.shared.u64 t, %1; cvt.u32.u64 %0, t; }"
        : "=r"(a) : "l"(p));
    return a;
}
__device__ __forceinline__ void ldsm4(uint32_t a, uint32_t r[4]) {
    asm volatile("ldmatrix.sync.aligned.m8n8.x4.shared.b16 {%0,%1,%2,%3}, [%4];"
                 : "=r"(r[0]), "=r"(r[1]), "=r"(r[2]), "=r"(r[3]) : "r"(a));
}
__device__ __forceinline__ void ldsm4t(uint32_t a, uint32_t r[4]) {
    asm volatile("ldmatrix.sync.aligned.m8n8.x4.trans.shared.b16 {%0,%1,%2,%3}, [%4];"
                 : "=r"(r[0]), "=r"(r[1]), "=r"(r[2]), "=r"(r[3]) : "r"(a));
}
__device__ __forceinline__ void mma_h(float d[4], const uint32_t a[4],
                                      uint32_t b0, uint32_t b1) {
    asm volatile(
        "mma.sync.aligned.m16n8k16.row.col.f32.f16.f16.f32 "
        "{%0,%1,%2,%3}, {%4,%5,%6,%7}, {%8,%9}, {%0,%1,%2,%3};"
        : "+f"(d[0]), "+f"(d[1]), "+f"(d[2]), "+f"(d[3])
        : "r"(a[0]), "r"(a[1]), "r"(a[2]), "r"(a[3]), "r"(b0), "r"(b1));
}
__device__ __forceinline__ uint32_t ex2_h2(uint32_t x) {
    uint32_t r;
    asm("ex2.approx.f16x2 %0, %1;" : "=r"(r) : "r"(x));
    return r;
}
__device__ __forceinline__ uint32_t hadd2u(uint32_t a, uint32_t b) {
    uint32_t r;
    asm("add.f16x2 %0, %1, %2;" : "=r"(r) : "r"(a), "r"(b));
    return r;
}
// tile rows are 128B (64 halves); 8 x 16B chunks, XOR swizzle
__device__ __forceinline__ uint32_t sw_off(int row, int chunk) {
    return (uint32_t)(row * 128 + ((chunk ^ (row & 7)) << 4));
}
#define CP16(dst, src) \
    asm volatile("cp.async.cg.shared.global [%0], [%1], 16;" :: "r"(dst), "l"(src))
#define CPC() asm volatile("cp.async.commit_group;" ::: "memory")
#define CPW0() asm volatile("cp.async.wait_group 0;" ::: "memory")

__device__ __forceinline__ uint32_t pack_h2(float a, float b) {
    __half2 h = __floats2half2_rn(a, b);
    return *(uint32_t*)&h;
}

// ---------------------------------------------------------------------------
// Fused conversion: X blocks then W-transpose blocks in one grid.
// ---------------------------------------------------------------------------
#define XBLK 18432   // 3 * (4*2048*768/4 float4 / 256)
__global__ __launch_bounds__(256) void conv_all(const float* __restrict__ e1,
                                                const float* __restrict__ e2,
                                                const float* __restrict__ e3,
                                                const float* __restrict__ Wq,
                                                const float* __restrict__ Wk,
                                                const float* __restrict__ Wv) {
    __shared__ float tile[32][33];
    const int bx = blockIdx.x;
    if (bx < XBLK) {
        const int mod = bx / 6144;
        const float* src = mod == 0 ? e1 : (mod == 1 ? e2 : e3);
        size_t idx = (size_t)(bx - mod * 6144) * 256 + threadIdx.x;
        const float4 v = ((const float4*)src)[idx];
        uint2 o = { pack_h2(v.x, v.y), pack_h2(v.z, v.w) };
        ((uint2*)g_X)[(size_t)mod * (NBATCH * SLEN * HDIM / 4) + idx] = o;
    } else {
        int wb = bx - XBLK;                        // < 24*2*36
        const int hh0 = (wb % 24) * 32;
        wb /= 24;
        const int d0 = (wb & 1) * 32;
        const int wh = wb >> 1;                    // which*12 + head
        const int which = wh / NHEADS, head = wh % NHEADS;
        const float* W = which == 0 ? Wq : (which == 1 ? Wk : Wv);
        const float* Ws = W + (size_t)head * HDIM * HD;
        const int tx = threadIdx.x & 31, ty = threadIdx.x >> 5;

        #pragma unroll
        for (int j = 0; j < 4; j++) {
            int hh = ty * 4 + j;
            tile[hh][tx] = Ws[(size_t)(hh0 + hh) * HD + d0 + tx];
        }
        __syncthreads();
        __half* dst = g_Wt + ((size_t)wh * HD + d0) * HDIM + hh0;
        #pragma unroll
        for (int j = 0; j < 4; j++) {
            int d = ty * 4 + j;
            dst[(size_t)d * HDIM + tx] = __float2half_rn(tile[tx][d]);
        }
    }
}

// ---------------------------------------------------------------------------
// Projection: block (sT 0..7, bh 0..47, which 0..2), 128 threads (4 warps),
// 256-row s-tile, 64 rows per warp (4 m-tiles). cp.async double-buffered.
// All three outputs (Q, K, V) stored in natural [bh][s][d] layout.
// ---------------------------------------------------------------------------
__global__ __launch_bounds__(128, 2) void proj_mma(const float* __restrict__ bq,
                                                   const float* __restrict__ bk,
                                                   const float* __restrict__ bv) {
    extern __shared__ char smraw[];
    char* sm = (char*)(((uintptr_t)smraw + 127) & ~(uintptr_t)127);
    char* Xb[2] = { sm, sm + 32768 };           // 32KB each (256 rows)
    char* Wb[2] = { sm + 65536, sm + 73728 };   // 8KB each

    const int tid = threadIdx.x, lane = tid & 31, wid = tid >> 5;
    const int sT = blockIdx.x, bh = blockIdx.y, which = blockIdx.z;
    const int b = bh / NHEADS, h = bh % NHEADS, g = h >> 2;

    const __half* Xg = g_X + ((size_t)(g * NBATCH + b) * SLEN + (size_t)sT * 256) * HDIM;
    const __half* Wg = g_Wt + ((size_t)(which * NHEADS + h) * HD) * HDIM;

    const uint32_t sX[2] = { smem_u32(Xb[0]), smem_u32(Xb[1]) };
    const uint32_t sW[2] = { smem_u32(Wb[0]), smem_u32(Wb[1]) };

    auto prefetch = [&](int ch, int bf) {
        #pragma unroll
        for (int i = tid; i < 2048; i += 128) {          // X: 256 rows x 8 chunks
            int r = i >> 3, c = i & 7;
            CP16(sX[bf] + sw_off(r, c), (const char*)(Xg + (size_t)r * HDIM + ch * 64 + c * 8));
        }
        #pragma unroll
        for (int i = tid; i < 512; i += 128) {           // W: 64 rows x 8 chunks
            int r = i >> 3, c = i & 7;
            CP16(sW[bf] + sw_off(r, c), (const char*)(Wg + (size_t)r * HDIM + ch * 64 + c * 8));
        }
    };

    prefetch(0, 0);
    CPC();
    CPW0();
    __syncthreads();

    const int aRow0 = wid * 64 + (lane & 15);
    const int aChk = lane >> 4;
    const int bRow = (lane & 7) + ((lane >> 4) << 3);
    const int bChk = (lane >> 3) & 1;

    float acc[4][8][4] = {};

    for (int ch = 0; ch < 12; ch++) {
        if (ch < 11) { prefetch(ch + 1, (ch + 1) & 1); CPC(); }
        const int bf = ch & 1;
        #pragma unroll
        for (int ks = 0; ks < 4; ks++) {
            uint32_t a[4][4];
            #pragma unroll
            for (int mt = 0; mt < 4; mt++)
                ldsm4(sX[bf] + sw_off(aRow0 + mt * 16, ks * 2 + aChk), a[mt]);
            #pragma unroll
            for (int np = 0; np < 4; np++) {
                uint32_t bfr[4];
                ldsm4(sW[bf] + sw_off(np * 16 + bRow, ks * 2 + bChk), bfr);
                #pragma unroll
                for (int mt = 0; mt < 4; mt++) {
                    mma_h(acc[mt][2 * np],     a[mt], bfr[0], bfr[1]);
                    mma_h(acc[mt][2 * np + 1], a[mt], bfr[2], bfr[3]);
                }
            }
        }
        if (ch < 11) { CPW0(); __syncthreads(); }
    }

    const float* bias = (which == 0 ? bq : (which == 1 ? bk : bv)) + h * HD;
    // Q pre-scale: 1/sqrt(64) * log2(e), so attention can use exp2.
    const float scale = (which == 0) ? 0.125f * 1.44269504f : 1.0f;
    __half* D = (which == 0 ? g_Q : (which == 1 ? g_K : g_V))
              + ((size_t)bh * SLEN + (size_t)sT * 256) * HD;

    #pragma unroll
    for (int mt = 0; mt < 4; mt++) {
        #pragma unroll
        for (int nt = 0; nt < 8; nt++) {
            int d = nt * 8 + 2 * (lane & 3);
            float b0 = bias[d], b1 = bias[d + 1];
            #pragma unroll
            for (int rr = 0; rr < 2; rr++) {
                int srow = wid * 64 + mt * 16 + (lane >> 2) + rr * 8;
                uint32_t v = pack_h2((acc[mt][nt][2 * rr] + b0) * scale,
                                     (acc[mt][nt][2 * rr + 1] + b1) * scale);
                *(uint32_t*)(D + (size_t)srow * HD + d) = v;
            }
        }
    }
}

// ---------------------------------------------------------------------------
// Attention: block (qT 0..15, bh 0..47), 128 threads (4 warps x 32 q-rows).
// 128-key outer tiles (one barrier each), two 64-key inner passes (R12 best).
// V in natural [s][d] layout; B-fragments via ldmatrix.trans.
// ---------------------------------------------------------------------------
__global__ __launch_bounds__(128, 2) void attn_mma(float* __restrict__ out) {
    extern __shared__ char smraw[];
    char* sm = (char*)(((uintptr_t)smraw + 127) & ~(uintptr_t)127);
    char* Qs = sm;                                               // 16KB
    char* Kst[2][2] = { { sm + 16384, sm + 24576 }, { sm + 32768, sm + 40960 } };
    char* Vst[2][2] = { { sm + 49152, sm + 57344 }, { sm + 65536, sm + 73728 } };

    const int tid = threadIdx.x, lane = tid & 31, wid = tid >> 5;
    const int qT = blockIdx.x, bh = blockIdx.y;
    const int b = bh / NHEADS, h = bh % NHEADS;

    const uint32_t sQ = smem_u32(Qs);
    uint32_t sK[2][2], sV[2][2];
    #pragma unroll
    for (int i = 0; i < 2; i++)
        #pragma unroll
        for (int j = 0; j < 2; j++) {
            sK[i][j] = smem_u32(Kst[i][j]);
            sV[i][j] = smem_u32(Vst[i][j]);
        }

    const __half* Qg = g_Q + ((size_t)bh * SLEN + (size_t)qT * 128) * HD;
    const __half* Kg = g_K + (size_t)bh * SLEN * HD;
    const __half* Vg = g_V + (size_t)bh * SLEN * HD;

    // Load one 128-key tile (two 64-key sub-tiles each for K and V).
    auto prefetch = [&](int t, int bf) {
        #pragma unroll
        for (int i = tid; i < 1024; i += 128) {          // K: 128 rows x 8 chunks
            int r = i >> 3, c = i & 7;
            CP16(sK[bf][r >> 6] + sw_off(r & 63, c),
                 (const char*)(Kg + ((size_t)t * 128 + r) * HD + c * 8));
        }
        #pragma unroll
        for (int i = tid; i < 1024; i += 128) {          // V: 128 rows x 8 chunks
            int r = i >> 3, c = i & 7;
            CP16(sV[bf][r >> 6] + sw_off(r & 63, c),
                 (const char*)(Vg + ((size_t)t * 128 + r) * HD + c * 8));
        }
    };

    #pragma unroll
    for (int i = tid; i < 1024; i += 128) {
        int r = i >> 3, c = i & 7;
        CP16(sQ + sw_off(r, c), (const char*)(Qg + (size_t)r * HD + c * 8));
    }
    prefetch(0, 0);
    CPC();
    CPW0();
    __syncthreads();

    const int aRow0 = wid * 32 + (lane & 15);
    const int aChk = lane >> 4;
    const int bRow = (lane & 7) + ((lane >> 4) << 3);
    const int bChk = (lane >> 3) & 1;
    const int cRow = lane & 15;          // for ldsm.trans (V)
    const int cChk = lane >> 4;

    // Hoist Q A-fragments (loop-invariant): 2 m-tiles x 4 k-steps
    uint32_t ahq[2][4][4];
    #pragma unroll
    for (int mt = 0; mt < 2; mt++)
        #pragma unroll
        for (int ks = 0; ks < 4; ks++)
            ldsm4(sQ + sw_off(aRow0 + mt * 16, ks * 2 + aChk), ahq[mt][ks]);

    float oacc[2][8][4] = {};
    float rs[2][2] = {};     // [mt][row-group], fp32 rowsum accumulators

    for (int t = 0; t < 16; t++) {
        if (t < 15) { prefetch(t + 1, (t + 1) & 1); CPC(); }
        const int bf = t & 1;

        #pragma unroll
        for (int hf = 0; hf < 2; hf++) {
            // S = Q K^T for this 64-key sub-tile
            float sacc[2][8][4] = {};
            #pragma unroll
            for (int ks = 0; ks < 4; ks++) {
                #pragma unroll
                for (int np = 0; np < 4; np++) {
                    uint32_t bfr[4];
                    ldsm4(sK[bf][hf] + sw_off(np * 16 + bRow, ks * 2 + bChk), bfr);
                    #pragma unroll
                    for (int mt = 0; mt < 2; mt++) {
                        mma_h(sacc[mt][2 * np],     ahq[mt][ks], bfr[0], bfr[1]);
                        mma_h(sacc[mt][2 * np + 1], ahq[mt][ks], bfr[2], bfr[3]);
                    }
                }
            }

            // Per m-tile: exp2 -> P frags, HADD2-tree rowsum, then PV MMAs.
            uint32_t ph[2][8][2];
            #pragma unroll
            for (int mt = 0; mt < 2; mt++) {
                #pragma unroll
                for (int nt = 0; nt < 8; nt++) {
                    ph[mt][nt][0] = ex2_h2(pack_h2(sacc[mt][nt][0], sacc[mt][nt][1]));
                    ph[mt][nt][1] = ex2_h2(pack_h2(sacc[mt][nt][2], sacc[mt][nt][3]));
                }
                #pragma unroll
                for (int rg = 0; rg < 2; rg++) {
                    uint32_t s = hadd2u(
                        hadd2u(hadd2u(ph[mt][0][rg], ph[mt][1][rg]),
                               hadd2u(ph[mt][2][rg], ph[mt][3][rg])),
                        hadd2u(hadd2u(ph[mt][4][rg], ph[mt][5][rg]),
                               hadd2u(ph[mt][6][rg], ph[mt][7][rg])));
                    float2 f = __half22float2(*(__half2*)&s);
                    rs[mt][rg] += f.x + f.y;
                }
                // O += P V; V B-frags via ldmatrix.trans from natural [t][d]
                #pragma unroll
                for (int ks = 0; ks < 4; ks++) {     // ks = 16-key group
                    uint32_t A[4] = { ph[mt][2 * ks][0],     ph[mt][2 * ks][1],
                                      ph[mt][2 * ks + 1][0], ph[mt][2 * ks + 1][1] };
                    #pragma unroll
                    for (int nv = 0; nv < 4; nv++) { // nv = 16-wide d group
                        uint32_t vf[4];
                        ldsm4t(sV[bf][hf] + sw_off(ks * 16 + cRow, nv * 2 + cChk), vf);
                        mma_h(oacc[mt][2 * nv],     A, vf[0], vf[1]);
                        mma_h(oacc[mt][2 * nv + 1], A, vf[2], vf[3]);
                    }
                }
            }
        }
        if (t < 15) { CPW0(); __syncthreads(); }
    }

    // Rowsum reduce across the quad (columns spread over lane%4)
    #pragma unroll
    for (int mt = 0; mt < 2; mt++)
        #pragma unroll
        for (int rg = 0; rg < 2; rg++) {
            float v = rs[mt][rg];
            v += __shfl_xor_sync(0xffffffffu, v, 1);
            v += __shfl_xor_sync(0xffffffffu, v, 2);
            rs[mt][rg] = v;
        }

    // Write output: out[b][s][h*64 + d]
    int r = lane >> 2;
    #pragma unroll
    for (int mt = 0; mt < 2; mt++) {
        float inv0 = 1.0f / rs[mt][0];
        float inv1 = 1.0f / rs[mt][1];
        int srow0 = qT * 128 + wid * 32 + mt * 16 + r;
        #pragma unroll
        for (int nt = 0; nt < 8; nt++) {
            int d = nt * 8 + 2 * (lane & 3);
            float2 v0 = { oacc[mt][nt][0] * inv0, oacc[mt][nt][1] * inv0 };
            float2 v1 = { oacc[mt][nt][2] * inv1, oacc[mt][nt][3] * inv1 };
            *(float2*)&out[((size_t)b * SLEN + srow0)     * HDIM + h * HD + d] = v0;
            *(float2*)&out[((size_t)b * SLEN + srow0 + 8) * HDIM + h * HD + d] = v1;
        }
    }
}

// ---------------------------------------------------------------------------
extern "C" void kernel_launch(void* const* d_in, const int* in_sizes, int n_in,
                              void* d_out, int out_size) {
    const float* e1 = (const float*)d_in[0];
    const float* e2 = (const float*)d_in[1];
    const float* e3 = (const float*)d_in[2];
    const float* Wq = (const float*)d_in[3];
    const float* bq = (const float*)d_in[4];
    const float* Wk = (const float*)d_in[5];
    const float* bk = (const float*)d_in[6];
    const float* Wv = (const float*)d_in[7];
    const float* bv = (const float*)d_in[8];
    float* out = (float*)d_out;

    conv_all<<<XBLK + 24 * 2 * 36, 256>>>(e1, e2, e3, Wq, Wk, Wv);

    const int smProj = 81920 + 256;
    const int smAttn = 81920 + 256;
    cudaFuncSetAttribute(proj_mma, cudaFuncAttributeMaxDynamicSharedMemorySize, smProj);
    cudaFuncSetAttribute(attn_mma, cudaFuncAttributeMaxDynamicSharedMemorySize, smAttn);

    proj_mma<<<dim3(8, 48, 3), 128, smProj>>>(bq, bk, bv);
    attn_mma<<<dim3(16, 48), 128, smAttn>>>(out);
}

// round 15
// speedup vs baseline: 1.0603x; 1.0273x over previous
#include <cuda_runtime.h>
#include <cuda_fp16.h>
#include <cstdint>

#define SLEN 2048
#define HDIM 768
#define HD 64
#define NHEADS 12
#define NBH 48
#define NBATCH 4

// fp16 scratch
__device__ __half g_X [(size_t)3 * NBATCH * SLEN * HDIM];   // [mod][b][s][h]
__device__ __half g_Wt[(size_t)3 * NHEADS * HD * HDIM];     // [which][head][d][h]
__device__ __half g_Q [(size_t)NBH * SLEN * HD];            // pre-scaled by 0.125*log2(e)
__device__ __half g_K [(size_t)NBH * SLEN * HD];
__device__ __half g_V [(size_t)NBH * SLEN * HD];            // natural [bh][s][d]

// ---------------------------------------------------------------------------
__device__ __forceinline__ uint32_t smem_u32(const void* p) {
    uint32_t a;
    asm("{ .reg .u64 t; cvta.to.shared.u64 t, %1; cvt.u32.u64 %0, t; }"
        : "=r"(a) : "l"(p));
    return a;
}
__device__ __forceinline__ void ldsm4(uint32_t a, uint32_t r[4]) {
    asm volatile("ldmatrix.sync.aligned.m8n8.x4.shared.b16 {%0,%1,%2,%3}, [%4];"
                 : "=r"(r[0]), "=r"(r[1]), "=r"(r[2]), "=r"(r[3]) : "r"(a));
}
__device__ __forceinline__ void ldsm4t(uint32_t a, uint32_t r[4]) {
    asm volatile("ldmatrix.sync.aligned.m8n8.x4.trans.shared.b16 {%0,%1,%2,%3}, [%4];"
                 : "=r"(r[0]), "=r"(r[1]), "=r"(r[2]), "=r"(r[3]) : "r"(a));
}
__device__ __forceinline__ void mma_h(float d[4], const uint32_t a[4],
                                      uint32_t b0, uint32_t b1) {
    asm volatile(
        "mma.sync.aligned.m16n8k16.row.col.f32.f16.f16.f32 "
        "{%0,%1,%2,%3}, {%4,%5,%6,%7}, {%8,%9}, {%0,%1,%2,%3};"
        : "+f"(d[0]), "+f"(d[1]), "+f"(d[2]), "+f"(d[3])
        : "r"(a[0]), "r"(a[1]), "r"(a[2]), "r"(a[3]), "r"(b0), "r"(b1));
}
__device__ __forceinline__ uint32_t ex2_h2(uint32_t x) {
    uint32_t r;
    asm("ex2.approx.f16x2 %0, %1;" : "=r"(r) : "r"(x));
    return r;
}
__device__ __forceinline__ uint32_t hadd2u(uint32_t a, uint32_t b) {
    uint32_t r;
    asm("add.f16x2 %0, %1, %2;" : "=r"(r) : "r"(a), "r"(b));
    return r;
}
// tile rows are 128B (64 halves); 8 x 16B chunks, XOR swizzle
__device__ __forceinline__ uint32_t sw_off(int row, int chunk) {
    return (uint32_t)(row * 128 + ((chunk ^ (row & 7)) << 4));
}
#define CP16(dst, src) \
    asm volatile("cp.async.cg.shared.global [%0], [%1], 16;" :: "r"(dst), "l"(src))
#define CPC() asm volatile("cp.async.commit_group;" ::: "memory")
#define CPW0() asm volatile("cp.async.wait_group 0;" ::: "memory")

__device__ __forceinline__ uint32_t pack_h2(float a, float b) {
    __half2 h = __floats2half2_rn(a, b);
    return *(uint32_t*)&h;
}

// ---------------------------------------------------------------------------
// Fused conversion: X blocks (4 float4/thread) then W-transpose blocks.
// ---------------------------------------------------------------------------
#define XBLK 4608    // 3 * (4*2048*768/4 float4 / (256*4))
__global__ __launch_bounds__(256) void conv_all(const float* __restrict__ e1,
                                                const float* __restrict__ e2,
                                                const float* __restrict__ e3,
                                                const float* __restrict__ Wq,
                                                const float* __restrict__ Wk,
                                                const float* __restrict__ Wv) {
    __shared__ float tile[32][33];
    const int bx = blockIdx.x;
    if (bx < XBLK) {
        const int mod = bx / 1536;
        const float* src = mod == 0 ? e1 : (mod == 1 ? e2 : e3);
        size_t base = (size_t)(bx - mod * 1536) * 1024 + threadIdx.x;
        uint2* dst = (uint2*)g_X + (size_t)mod * (NBATCH * SLEN * HDIM / 4);
        #pragma unroll
        for (int j = 0; j < 4; j++) {
            size_t idx = base + j * 256;
            const float4 v = ((const float4*)src)[idx];
            uint2 o = { pack_h2(v.x, v.y), pack_h2(v.z, v.w) };
            dst[idx] = o;
        }
    } else {
        int wb = bx - XBLK;                        // < 24*2*36
        const int hh0 = (wb % 24) * 32;
        wb /= 24;
        const int d0 = (wb & 1) * 32;
        const int wh = wb >> 1;                    // which*12 + head
        const int which = wh / NHEADS, head = wh % NHEADS;
        const float* W = which == 0 ? Wq : (which == 1 ? Wk : Wv);
        const float* Ws = W + (size_t)head * HDIM * HD;
        const int tx = threadIdx.x & 31, ty = threadIdx.x >> 5;

        #pragma unroll
        for (int j = 0; j < 4; j++) {
            int hh = ty * 4 + j;
            tile[hh][tx] = Ws[(size_t)(hh0 + hh) * HD + d0 + tx];
        }
        __syncthreads();
        __half* dst = g_Wt + ((size_t)wh * HD + d0) * HDIM + hh0;
        #pragma unroll
        for (int j = 0; j < 4; j++) {
            int d = ty * 4 + j;
            dst[(size_t)d * HDIM + tx] = __float2half_rn(tile[tx][d]);
        }
    }
}

// ---------------------------------------------------------------------------
// Projection: block (sT 0..7, bh 0..47, which 0..2), 128 threads (4 warps),
// 256-row s-tile, 64 rows per warp (4 m-tiles). cp.async double-buffered.
// All three outputs (Q, K, V) stored in natural [bh][s][d] layout.
// ---------------------------------------------------------------------------
__global__ __launch_bounds__(128, 2) void proj_mma(const float* __restrict__ bq,
                                                   const float* __restrict__ bk,
                                                   const float* __restrict__ bv) {
    extern __shared__ char smraw[];
    char* sm = (char*)(((uintptr_t)smraw + 127) & ~(uintptr_t)127);
    char* Xb[2] = { sm, sm + 32768 };           // 32KB each (256 rows)
    char* Wb[2] = { sm + 65536, sm + 73728 };   // 8KB each

    const int tid = threadIdx.x, lane = tid & 31, wid = tid >> 5;
    const int sT = blockIdx.x, bh = blockIdx.y, which = blockIdx.z;
    const int b = bh / NHEADS, h = bh % NHEADS, g = h >> 2;

    const __half* Xg = g_X + ((size_t)(g * NBATCH + b) * SLEN + (size_t)sT * 256) * HDIM;
    const __half* Wg = g_Wt + ((size_t)(which * NHEADS + h) * HD) * HDIM;

    const uint32_t sX[2] = { smem_u32(Xb[0]), smem_u32(Xb[1]) };
    const uint32_t sW[2] = { smem_u32(Wb[0]), smem_u32(Wb[1]) };

    auto prefetch = [&](int ch, int bf) {
        #pragma unroll
        for (int i = tid; i < 2048; i += 128) {          // X: 256 rows x 8 chunks
            int r = i >> 3, c = i & 7;
            CP16(sX[bf] + sw_off(r, c), (const char*)(Xg + (size_t)r * HDIM + ch * 64 + c * 8));
        }
        #pragma unroll
        for (int i = tid; i < 512; i += 128) {           // W: 64 rows x 8 chunks
            int r = i >> 3, c = i & 7;
            CP16(sW[bf] + sw_off(r, c), (const char*)(Wg + (size_t)r * HDIM + ch * 64 + c * 8));
        }
    };

    prefetch(0, 0);
    CPC();
    CPW0();
    __syncthreads();

    const int aRow0 = wid * 64 + (lane & 15);
    const int aChk = lane >> 4;
    const int bRow = (lane & 7) + ((lane >> 4) << 3);
    const int bChk = (lane >> 3) & 1;

    float acc[4][8][4] = {};

    for (int ch = 0; ch < 12; ch++) {
        if (ch < 11) { prefetch(ch + 1, (ch + 1) & 1); CPC(); }
        const int bf = ch & 1;
        #pragma unroll
        for (int ks = 0; ks < 4; ks++) {
            uint32_t a[4][4];
            #pragma unroll
            for (int mt = 0; mt < 4; mt++)
                ldsm4(sX[bf] + sw_off(aRow0 + mt * 16, ks * 2 + aChk), a[mt]);
            #pragma unroll
            for (int np = 0; np < 4; np++) {
                uint32_t bfr[4];
                ldsm4(sW[bf] + sw_off(np * 16 + bRow, ks * 2 + bChk), bfr);
                #pragma unroll
                for (int mt = 0; mt < 4; mt++) {
                    mma_h(acc[mt][2 * np],     a[mt], bfr[0], bfr[1]);
                    mma_h(acc[mt][2 * np + 1], a[mt], bfr[2], bfr[3]);
                }
            }
        }
        if (ch < 11) { CPW0(); __syncthreads(); }
    }

    const float* bias = (which == 0 ? bq : (which == 1 ? bk : bv)) + h * HD;
    // Q pre-scale: 1/sqrt(64) * log2(e), so attention can use exp2.
    const float scale = (which == 0) ? 0.125f * 1.44269504f : 1.0f;
    __half* D = (which == 0 ? g_Q : (which == 1 ? g_K : g_V))
              + ((size_t)bh * SLEN + (size_t)sT * 256) * HD;

    #pragma unroll
    for (int mt = 0; mt < 4; mt++) {
        #pragma unroll
        for (int nt = 0; nt < 8; nt++) {
            int d = nt * 8 + 2 * (lane & 3);
            float b0 = bias[d], b1 = bias[d + 1];
            #pragma unroll
            for (int rr = 0; rr < 2; rr++) {
                int srow = wid * 64 + mt * 16 + (lane >> 2) + rr * 8;
                uint32_t v = pack_h2((acc[mt][nt][2 * rr] + b0) * scale,
                                     (acc[mt][nt][2 * rr + 1] + b1) * scale);
                *(uint32_t*)(D + (size_t)srow * HD + d) = v;
            }
        }
    }
}

// ---------------------------------------------------------------------------
// Attention: block (qT 0..15, bh 0..47), 128 threads (4 warps x 32 q-rows).
// 128-key outer tiles (one barrier each), two 64-key inner passes.
// Q fragments loaded from smem inside the QK loop (lower register pressure).
// V in natural [s][d] layout; B-fragments via ldmatrix.trans.
// ---------------------------------------------------------------------------
__global__ __launch_bounds__(128, 2) void attn_mma(float* __restrict__ out) {
    extern __shared__ char smraw[];
    char* sm = (char*)(((uintptr_t)smraw + 127) & ~(uintptr_t)127);
    char* Qs = sm;                                               // 16KB
    char* Kst[2][2] = { { sm + 16384, sm + 24576 }, { sm + 32768, sm + 40960 } };
    char* Vst[2][2] = { { sm + 49152, sm + 57344 }, { sm + 65536, sm + 73728 } };

    const int tid = threadIdx.x, lane = tid & 31, wid = tid >> 5;
    const int qT = blockIdx.x, bh = blockIdx.y;
    const int b = bh / NHEADS, h = bh % NHEADS;

    const uint32_t sQ = smem_u32(Qs);
    uint32_t sK[2][2], sV[2][2];
    #pragma unroll
    for (int i = 0; i < 2; i++)
        #pragma unroll
        for (int j = 0; j < 2; j++) {
            sK[i][j] = smem_u32(Kst[i][j]);
            sV[i][j] = smem_u32(Vst[i][j]);
        }

    const __half* Qg = g_Q + ((size_t)bh * SLEN + (size_t)qT * 128) * HD;
    const __half* Kg = g_K + (size_t)bh * SLEN * HD;
    const __half* Vg = g_V + (size_t)bh * SLEN * HD;

    // Load one 128-key tile (two 64-key sub-tiles each for K and V).
    auto prefetch = [&](int t, int bf) {
        #pragma unroll
        for (int i = tid; i < 1024; i += 128) {          // K: 128 rows x 8 chunks
            int r = i >> 3, c = i & 7;
            CP16(sK[bf][r >> 6] + sw_off(r & 63, c),
                 (const char*)(Kg + ((size_t)t * 128 + r) * HD + c * 8));
        }
        #pragma unroll
        for (int i = tid; i < 1024; i += 128) {          // V: 128 rows x 8 chunks
            int r = i >> 3, c = i & 7;
            CP16(sV[bf][r >> 6] + sw_off(r & 63, c),
                 (const char*)(Vg + ((size_t)t * 128 + r) * HD + c * 8));
        }
    };

    #pragma unroll
    for (int i = tid; i < 1024; i += 128) {
        int r = i >> 3, c = i & 7;
        CP16(sQ + sw_off(r, c), (const char*)(Qg + (size_t)r * HD + c * 8));
    }
    prefetch(0, 0);
    CPC();
    CPW0();
    __syncthreads();

    const int aRow0 = wid * 32 + (lane & 15);
    const int aChk = lane >> 4;
    const int bRow = (lane & 7) + ((lane >> 4) << 3);
    const int bChk = (lane >> 3) & 1;
    const int cRow = lane & 15;          // for ldsm.trans (V)
    const int cChk = lane >> 4;

    float oacc[2][8][4] = {};
    float rs[2][2] = {};     // [mt][row-group], fp32 rowsum accumulators

    for (int t = 0; t < 16; t++) {
        if (t < 15) { prefetch(t + 1, (t + 1) & 1); CPC(); }
        const int bf = t & 1;

        #pragma unroll
        for (int hf = 0; hf < 2; hf++) {
            // S = Q K^T for this 64-key sub-tile; Q frags loaded per ks.
            float sacc[2][8][4] = {};
            #pragma unroll
            for (int ks = 0; ks < 4; ks++) {
                uint32_t aq[2][4];
                #pragma unroll
                for (int mt = 0; mt < 2; mt++)
                    ldsm4(sQ + sw_off(aRow0 + mt * 16, ks * 2 + aChk), aq[mt]);
                #pragma unroll
                for (int np = 0; np < 4; np++) {
                    uint32_t bfr[4];
                    ldsm4(sK[bf][hf] + sw_off(np * 16 + bRow, ks * 2 + bChk), bfr);
                    #pragma unroll
                    for (int mt = 0; mt < 2; mt++) {
                        mma_h(sacc[mt][2 * np],     aq[mt], bfr[0], bfr[1]);
                        mma_h(sacc[mt][2 * np + 1], aq[mt], bfr[2], bfr[3]);
                    }
                }
            }

            // Per m-tile: exp2 -> P frags, HADD2-tree rowsum, then PV MMAs.
            #pragma unroll
            for (int mt = 0; mt < 2; mt++) {
                uint32_t ph[8][2];
                #pragma unroll
                for (int nt = 0; nt < 8; nt++) {
                    ph[nt][0] = ex2_h2(pack_h2(sacc[mt][nt][0], sacc[mt][nt][1]));
                    ph[nt][1] = ex2_h2(pack_h2(sacc[mt][nt][2], sacc[mt][nt][3]));
                }
                #pragma unroll
                for (int rg = 0; rg < 2; rg++) {
                    uint32_t s = hadd2u(
                        hadd2u(hadd2u(ph[0][rg], ph[1][rg]),
                               hadd2u(ph[2][rg], ph[3][rg])),
                        hadd2u(hadd2u(ph[4][rg], ph[5][rg]),
                               hadd2u(ph[6][rg], ph[7][rg])));
                    float2 f = __half22float2(*(__half2*)&s);
                    rs[mt][rg] += f.x + f.y;
                }
                // O += P V; V B-frags via ldmatrix.trans from natural [t][d]
                #pragma unroll
                for (int ks = 0; ks < 4; ks++) {     // ks = 16-key group
                    uint32_t A[4] = { ph[2 * ks][0],     ph[2 * ks][1],
                                      ph[2 * ks + 1][0], ph[2 * ks + 1][1] };
                    #pragma unroll
                    for (int nv = 0; nv < 4; nv++) { // nv = 16-wide d group
                        uint32_t vf[4];
                        ldsm4t(sV[bf][hf] + sw_off(ks * 16 + cRow, nv * 2 + cChk), vf);
                        mma_h(oacc[mt][2 * nv],     A, vf[0], vf[1]);
                        mma_h(oacc[mt][2 * nv + 1], A, vf[2], vf[3]);
                    }
                }
            }
        }
        if (t < 15) { CPW0(); __syncthreads(); }
    }

    // Rowsum reduce across the quad (columns spread over lane%4)
    #pragma unroll
    for (int mt = 0; mt < 2; mt++)
        #pragma unroll
        for (int rg = 0; rg < 2; rg++) {
            float v = rs[mt][rg];
            v += __shfl_xor_sync(0xffffffffu, v, 1);
            v += __shfl_xor_sync(0xffffffffu, v, 2);
            rs[mt][rg] = v;
        }

    // Write output: out[b][s][h*64 + d]
    int r = lane >> 2;
    #pragma unroll
    for (int mt = 0; mt < 2; mt++) {
        float inv0 = 1.0f / rs[mt][0];
        float inv1 = 1.0f / rs[mt][1];
        int srow0 = qT * 128 + wid * 32 + mt * 16 + r;
        #pragma unroll
        for (int nt = 0; nt < 8; nt++) {
            int d = nt * 8 + 2 * (lane & 3);
            float2 v0 = { oacc[mt][nt][0] * inv0, oacc[mt][nt][1] * inv0 };
            float2 v1 = { oacc[mt][nt][2] * inv1, oacc[mt][nt][3] * inv1 };
            *(float2*)&out[((size_t)b * SLEN + srow0)     * HDIM + h * HD + d] = v0;
            *(float2*)&out[((size_t)b * SLEN + srow0 + 8) * HDIM + h * HD + d] = v1;
        }
    }
}

// ---------------------------------------------------------------------------
extern "C" void kernel_launch(void* const* d_in, const int* in_sizes, int n_in,
                              void* d_out, int out_size) {
    const float* e1 = (const float*)d_in[0];
    const float* e2 = (const float*)d_in[1];
    const float* e3 = (const float*)d_in[2];
    const float* Wq = (const float*)d_in[3];
    const float* bq = (const float*)d_in[4];
    const float* Wk = (const float*)d_in[5];
    const float* bk = (const float*)d_in[6];
    const float* Wv = (const float*)d_in[7];
    const float* bv = (const float*)d_in[8];
    float* out = (float*)d_out;

    conv_all<<<XBLK + 24 * 2 * 36, 256>>>(e1, e2, e3, Wq, Wk, Wv);

    const int smProj = 81920 + 256;
    const int smAttn = 81920 + 256;
    cudaFuncSetAttribute(proj_mma, cudaFuncAttributeMaxDynamicSharedMemorySize, smProj);
    cudaFuncSetAttribute(attn_mma, cudaFuncAttributeMaxDynamicSharedMemorySize, smAttn);

    proj_mma<<<dim3(8, 48, 3), 128, smProj>>>(bq, bk, bv);
    attn_mma<<<dim3(16, 48), 128, smAttn>>>(out);
}